// round 11
// baseline (speedup 1.0000x reference)
#include <cuda_runtime.h>
#include <math.h>
#include <stdint.h>

#define NN   32768
#define EE   1048576
#define NSD  64
#define NVD  32
#define LATD 256

// ---- scales ----
#define INV8    0.125f                 // 1/sqrt(64)
#define C1      0.10206207261596575f   // (1/sqrt(3))/sqrt(32) = 1/sqrt(96)
#define INV_R2  0.7071067811865476f
#define INVS32  0.17677669529663687f   // 1/sqrt(32)
#define S_USS   0.011048543456039806f  // 1/(64*sqrt(2))
#define S_UVV   0.012757998811063534f  // 1/(32*sqrt(6))
#define S_V     0.015625f              // 1/sqrt(64*32*2) = 1/64

typedef unsigned long long ull;

// ---- scratch (device globals; no allocation) ----
__device__ float g_ns[NN * NSD];
__device__ float g_nv[NN * NVD * 3];
__device__ float g_NF[(size_t)NN * 384];  // SS(64)|Q(3x64)|SV(32)|VS(3x32)
__device__ float g_as[NN * NSD];
__device__ float g_av[NN * NVD * 3];

__device__ __forceinline__ float sigmf(float x) { return 1.0f / (1.0f + __expf(-x)); }

// ---- packed f32x2 helpers ----
__device__ __forceinline__ void ffma2(ull& d, ull a, ull b) {
    asm("fma.rn.f32x2 %0, %1, %2, %0;" : "+l"(d) : "l"(a), "l"(b));
}
__device__ __forceinline__ ull fadd2(ull a, ull b) {
    ull r; asm("add.rn.f32x2 %0, %1, %2;" : "=l"(r) : "l"(a), "l"(b)); return r;
}
__device__ __forceinline__ ull pack2(float x, float y) {
    ull r;
    asm("mov.b64 %0, {%1, %2};" : "=l"(r)
        : "r"(__float_as_uint(x)), "r"(__float_as_uint(y)));
    return r;
}
__device__ __forceinline__ float2 unpack2(ull v) {
    unsigned int lo, hi;
    asm("mov.b64 {%0, %1}, %2;" : "=r"(lo), "=r"(hi) : "l"(v));
    return make_float2(__uint_as_float(lo), __uint_as_float(hi));
}

// ============================ k_in: ns = x @ W_in / 8 ============================
__global__ __launch_bounds__(256) void k_in(const float* __restrict__ x,
                                            const float* __restrict__ Win) {
    __shared__ float xs[32 * 65];
    __shared__ float ws[64 * 64];
    const int tid = threadIdx.x;
    const int node0 = blockIdx.x * 32;
    const float4* wg = (const float4*)Win;
    float4* ws4 = (float4*)ws;
#pragma unroll
    for (int r = 0; r < 4; r++) ws4[tid + r * 256] = wg[tid + r * 256];
#pragma unroll
    for (int r = 0; r < 8; r++) {
        int lin = tid + r * 256; int t = lin >> 6, i = lin & 63;
        xs[t * 65 + i] = x[(size_t)(node0 + t) * 64 + i];
    }
    __syncthreads();
    const int o = tid & 63, tq = tid >> 6;
    float acc[8] = {0, 0, 0, 0, 0, 0, 0, 0};
#pragma unroll 16
    for (int i = 0; i < 64; i++) {
        float w = ws[i * 64 + o];
#pragma unroll
        for (int tt = 0; tt < 8; tt++) acc[tt] += xs[(tq * 8 + tt) * 65 + i] * w;
    }
#pragma unroll
    for (int tt = 0; tt < 8; tt++)
        g_ns[(size_t)(node0 + tq * 8 + tt) * 64 + o] = acc[tt] * INV8;
}

// ============== k_feat: per-node precompute SS, Q, SV, VS ==============
__global__ __launch_bounds__(256) void k_feat(const float* __restrict__ Wss,
                                              const float* __restrict__ Wvv0,
                                              const float* __restrict__ Wsv,
                                              const float* __restrict__ Wvs) {
    __shared__ float s_wss[64 * 64];
    __shared__ float s_wvv[32 * 64];
    __shared__ float s_wsv[64 * 32];
    __shared__ float s_wvs[32 * 32];
    __shared__ float s_ns[8][64];
    __shared__ float s_nv[8][96];
    const int tid = threadIdx.x;
    for (int i = tid; i < 4096; i += 256) s_wss[i] = Wss[i];
    for (int i = tid; i < 2048; i += 256) s_wvv[i] = Wvv0[i];
    for (int i = tid; i < 2048; i += 256) s_wsv[i] = Wsv[i];
    for (int i = tid; i < 1024; i += 256) s_wvs[i] = Wvs[i];
    const int w = tid >> 5, lane = tid & 31;
    const int node = blockIdx.x * 8 + w;
#pragma unroll
    for (int r = 0; r < 2; r++) s_ns[w][lane + 32 * r] = g_ns[(size_t)node * 64 + lane + 32 * r];
#pragma unroll
    for (int r = 0; r < 3; r++) s_nv[w][lane + 32 * r] = g_nv[(size_t)node * 96 + lane + 32 * r];
    __syncthreads();
    float* nf = g_NF + (size_t)node * 384;
#pragma unroll
    for (int h = 0; h < 2; h++) {
        int o = lane + 32 * h;
        float a = 0;
#pragma unroll 8
        for (int i = 0; i < 64; i++) a += s_ns[w][i] * s_wss[i * 64 + o];
        nf[o] = a;
    }
#pragma unroll
    for (int xx = 0; xx < 3; xx++) {
#pragma unroll
        for (int h = 0; h < 2; h++) {
            int o = lane + 32 * h;
            float a = 0;
#pragma unroll 8
            for (int m = 0; m < 32; m++) a += s_nv[w][m * 3 + xx] * s_wvv[m * 64 + o];
            nf[64 + xx * 64 + o] = a;
        }
    }
    {
        float a = 0;
#pragma unroll 8
        for (int i = 0; i < 64; i++) a += s_ns[w][i] * s_wsv[i * 32 + lane];
        nf[256 + lane] = a;
    }
#pragma unroll
    for (int xx = 0; xx < 3; xx++) {
        float a = 0;
#pragma unroll 8
        for (int m = 0; m < 32; m++) a += s_nv[w][m * 3 + xx] * s_wvs[m * 32 + lane];
        nf[288 + xx * 32 + lane] = a;
    }
}

// ================= k_edge: per-edge message + gate + scatter-add =================
__global__ __launch_bounds__(256) void k_edge(const float* __restrict__ eattr,
                                              const int* __restrict__ eidx,
                                              const float* __restrict__ gmw,
                                              const float* __restrict__ gmb) {
    __shared__ float s_gw[96], s_gb[96];
    const int tid = threadIdx.x;
    if (tid < 96) { s_gw[tid] = gmw[tid]; s_gb[tid] = gmb[tid]; }
    __syncthreads();
    const int w = tid >> 5, lane = tid & 31;
    const int e = blockIdx.x * 8 + w;
    const int r = eidx[e];
    const int c = eidx[EE + e];
    const float ev0 = eattr[(size_t)e * 4 + 0];
    const float ev1 = eattr[(size_t)e * 4 + 1];
    const float ev2 = eattr[(size_t)e * 4 + 2];
    const float es  = eattr[(size_t)e * 4 + 3];
    const float* nf = g_NF + (size_t)c * 384;
    float ms[2];
#pragma unroll
    for (int h = 0; h < 2; h++) {
        int o = lane + 32 * h;
        float dot = ev0 * nf[64 + o] + ev1 * nf[128 + o] + ev2 * nf[192 + o];
        float v = (es * nf[o] * INV8 + dot * C1) * INV_R2;
        ms[h] = v * sigmf(v);
    }
    const float sv = nf[256 + lane];
    float mv0 = (sv * ev0 * INV8 + es * nf[288 + lane] * INVS32) * INV_R2;
    float mv1 = (sv * ev1 * INV8 + es * nf[320 + lane] * INVS32) * INV_R2;
    float mv2 = (sv * ev2 * INV8 + es * nf[352 + lane] * INVS32) * INV_R2;
    float p = mv0 + mv1 + mv2;
#pragma unroll
    for (int off = 16; off; off >>= 1) p += __shfl_xor_sync(0xffffffffu, p, off);
    const float mean = p * (1.0f / 96.0f);
    const float g0 = sigmf(mean * s_gw[lane * 3 + 0] + s_gb[lane * 3 + 0]);
    const float g1 = sigmf(mean * s_gw[lane * 3 + 1] + s_gb[lane * 3 + 1]);
    const float g2 = sigmf(mean * s_gw[lane * 3 + 2] + s_gb[lane * 3 + 2]);
    float* as = g_as + (size_t)r * 64;
    float* av = g_av + (size_t)r * 96;
    atomicAdd(as + lane,        ms[0]);
    atomicAdd(as + lane + 32,   ms[1]);
    atomicAdd(av + lane * 3 + 0, mv0 * g0);
    atomicAdd(av + lane * 3 + 1, mv1 * g1);
    atomicAdd(av + lane * 3 + 2, mv2 * g2);
}

// ====== k_bilin: four bilinears + gate + residual ======
// 64 nodes / block, 256 threads, 2 blocks/SM. R10 inner loop, now SOFTWARE-PIPELINED:
// kb=16 chunks, double-buffered scratch, stage(c+1) overlaps compute(c), 1 barrier/chunk.
// smem floats: ns 4160 | as 4160 | nv 6208 | av 6208 | scr 7168 = 27904 (109KB)
#define BILIN_SMEM (27904 * 4)

__global__ __launch_bounds__(256, 2) void k_bilin(const float* __restrict__ Wuss,
                                                  const float* __restrict__ Wuvv,
                                                  const float* __restrict__ Wusv,
                                                  const float* __restrict__ Wuvs,
                                                  const float* __restrict__ guw,
                                                  const float* __restrict__ gub) {
    extern __shared__ float sm[];
    float* ns_s = sm;                 // [64][65]
    float* as_s = sm + 4160;          // [64][65]
    float* nv_s = sm + 8320;          // [64][97]
    float* av_s = sm + 14528;         // [64][97]
    float* scr  = sm + 20736;         // 7168 floats: double-buffered W+A staging
    const int tid = threadIdx.x;
    const int node0 = blockIdx.x * 64;

    // ---- load node data (vectorized) ----
    {
        const float4* gns = (const float4*)(g_ns + (size_t)node0 * 64);
        const float4* gas = (const float4*)(g_as + (size_t)node0 * 64);
#pragma unroll
        for (int r = 0; r < 4; r++) {
            int lin = tid + r * 256; int t = lin >> 4, c = lin & 15;
            float4 v = gns[lin];
            float4 u = gas[lin];
            float* pd = ns_s + t * 65 + c * 4;
            pd[0] = v.x; pd[1] = v.y; pd[2] = v.z; pd[3] = v.w;
            float* qd = as_s + t * 65 + c * 4;
            qd[0] = u.x; qd[1] = u.y; qd[2] = u.z; qd[3] = u.w;
        }
        const float4* gnv = (const float4*)(g_nv + (size_t)node0 * 96);
        const float4* gav = (const float4*)(g_av + (size_t)node0 * 96);
#pragma unroll
        for (int r = 0; r < 6; r++) {
            int lin = tid + r * 256; int t = lin / 24, c = lin % 24;
            float4 v = gnv[lin];
            float4 u = gav[lin];
            float* pd = nv_s + t * 97 + c * 4;
            pd[0] = v.x; pd[1] = v.y; pd[2] = v.z; pd[3] = v.w;
            float* qd = av_s + t * 97 + c * 4;
            qd[0] = u.x; qd[1] = u.y; qd[2] = u.z; qd[3] = u.w;
        }
    }
    __syncthreads();

    // ================ Phase A: u_s = uss + uvv ================
    // thread tile: 4 outs (tx) x 4 nodes (ty, as 2 f32x2 pairs)
    const int tx = tid & 15, ty = tid >> 4;
    // double buffers: each = W[16][64] (1024) + A[16][64] (1024)
    float* Wbuf[2] = {scr, scr + 2048};
    float* Abuf[2] = {scr + 1024, scr + 3072};
    ull acc[8];
#pragma unroll
    for (int q = 0; q < 8; q++) acc[q] = 0ull;

    auto STAGE_USS = [&](int c, float* Wd, float* Ad) {
        const int kb = c * 16;
        float4 w = ((const float4*)(Wuss + (size_t)kb * 64))[tid];
        w.x *= S_USS; w.y *= S_USS; w.z *= S_USS; w.w *= S_USS;
        ((float4*)Wd)[tid] = w;
#pragma unroll
        for (int rr = 0; rr < 4; rr++) {
            int lin = tid + rr * 256; int kk = lin >> 6, t = lin & 63;
            int k = kb + kk; int i = k >> 6, j = k & 63;
            Ad[kk * 64 + t] = ns_s[t * 65 + i] * as_s[t * 65 + j];
        }
    };
    auto STAGE_UVV = [&](int c, float* Wd, float* Ad) {
        const int kb = c * 16;               // 0..3071
        const int xx = kb >> 10, km = kb & 1023;
        float4 w = ((const float4*)(Wuvv + (size_t)km * 64))[tid];
        w.x *= S_UVV; w.y *= S_UVV; w.z *= S_UVV; w.w *= S_UVV;
        ((float4*)Wd)[tid] = w;
#pragma unroll
        for (int rr = 0; rr < 4; rr++) {
            int lin = tid + rr * 256; int kk = lin >> 6, t = lin & 63;
            int k = km + kk; int m = k >> 5, n = k & 31;
            Ad[kk * 64 + t] = nv_s[t * 97 + m * 3 + xx] * av_s[t * 97 + n * 3 + xx];
        }
    };
    auto COMPUTE_A = [&](const float* Ws, const float* As) {
#pragma unroll
        for (int kk = 0; kk < 16; kk++) {
            ulonglong2 a2 = *(const ulonglong2*)(As + kk * 64 + ty * 4);
            float4 w4 = *(const float4*)(Ws + kk * 64 + tx * 4);
            ull wx = pack2(w4.x, w4.x), wy = pack2(w4.y, w4.y);
            ull wz = pack2(w4.z, w4.z), ww = pack2(w4.w, w4.w);
            ffma2(acc[0], a2.x, wx); ffma2(acc[1], a2.x, wy);
            ffma2(acc[2], a2.x, wz); ffma2(acc[3], a2.x, ww);
            ffma2(acc[4], a2.y, wx); ffma2(acc[5], a2.y, wy);
            ffma2(acc[6], a2.y, wz); ffma2(acc[7], a2.y, ww);
        }
    };

    STAGE_USS(0, Wbuf[0], Abuf[0]);
    __syncthreads();
#pragma unroll 1
    for (int c = 0; c < 256; c++) {               // uss: K=4096 in 16-chunks
        int cur = c & 1, nxt = cur ^ 1;
        if (c < 255) STAGE_USS(c + 1, Wbuf[nxt], Abuf[nxt]);
        else         STAGE_UVV(0, Wbuf[nxt], Abuf[nxt]);
        COMPUTE_A(Wbuf[cur], Abuf[cur]);
        __syncthreads();
    }
#pragma unroll 1
    for (int c = 0; c < 192; c++) {               // uvv: K=3072 in 16-chunks
        int cur = (c + 256) & 1, nxt = cur ^ 1;
        if (c < 191) STAGE_UVV(c + 1, Wbuf[nxt], Abuf[nxt]);
        COMPUTE_A(Wbuf[cur], Abuf[cur]);
        __syncthreads();
    }

    // u_s epilogue: silu + residual -> global ns (smem ns_s stays intact for phase B)
#pragma unroll
    for (int g = 0; g < 2; g++) {
#pragma unroll
        for (int q = 0; q < 4; q++) {
            float2 u = unpack2(acc[g * 4 + q]);
            int o = tx * 4 + q;
            int t0 = ty * 4 + g * 2;
            float s0 = u.x * sigmf(u.x);
            float s1 = u.y * sigmf(u.y);
            g_ns[(size_t)(node0 + t0) * 64 + o]     = ns_s[t0 * 65 + o] + s0;
            g_ns[(size_t)(node0 + t0 + 1) * 64 + o] = ns_s[(t0 + 1) * 65 + o] + s1;
        }
    }

    // ================ Phase B: u_v = usv + uvs ================
    // thread tile: 4 outs (txB) x 2 nodes (f32x2 pair, tyB) x 3 x-components
    const int txB = tid & 7, tyB = tid >> 3;
    // double buffers: each = W[16][32] (512) + A[3][16][64] (3072) = 3584
    float* WBb[2] = {scr, scr + 3584};
    float* ABb[2] = {scr + 512, scr + 4096};
    ull vacc[12];
#pragma unroll
    for (int q = 0; q < 12; q++) vacc[q] = 0ull;

    auto STAGE_USV = [&](int c, float* Wd, float* Ad) {
        const int kb = c * 16;
        float2 w = ((const float2*)(Wusv + (size_t)kb * 32))[tid];
        w.x *= S_V; w.y *= S_V;
        ((float2*)Wd)[tid] = w;
#pragma unroll
        for (int rr = 0; rr < 12; rr++) {
            int lin = tid + rr * 256;
            int xx = lin >> 10; int rem = lin & 1023; int kk = rem >> 6, t = rem & 63;
            int k = kb + kk; int i = k >> 5, n = k & 31;
            Ad[xx * 1024 + kk * 64 + t] = ns_s[t * 65 + i] * av_s[t * 97 + n * 3 + xx];
        }
    };
    auto STAGE_UVS = [&](int c, float* Wd, float* Ad) {
        const int kb = c * 16;
        float2 w = ((const float2*)(Wuvs + (size_t)kb * 32))[tid];
        w.x *= S_V; w.y *= S_V;
        ((float2*)Wd)[tid] = w;
#pragma unroll
        for (int rr = 0; rr < 12; rr++) {
            int lin = tid + rr * 256;
            int xx = lin >> 10; int rem = lin & 1023; int kk = rem >> 6, t = rem & 63;
            int k = kb + kk; int m = k >> 6, j = k & 63;
            Ad[xx * 1024 + kk * 64 + t] = nv_s[t * 97 + m * 3 + xx] * as_s[t * 65 + j];
        }
    };
    auto COMPUTE_B = [&](const float* Ws, const float* As) {
#pragma unroll
        for (int kk = 0; kk < 16; kk++) {
            float4 w4 = *(const float4*)(Ws + kk * 32 + txB * 4);
            ull w0 = pack2(w4.x, w4.x), w1 = pack2(w4.y, w4.y);
            ull w2 = pack2(w4.z, w4.z), w3 = pack2(w4.w, w4.w);
            ull a0 = *(const ull*)(As + kk * 64 + tyB * 2);
            ull a1 = *(const ull*)(As + 1024 + kk * 64 + tyB * 2);
            ull a2 = *(const ull*)(As + 2048 + kk * 64 + tyB * 2);
            ffma2(vacc[0],  a0, w0); ffma2(vacc[1],  a0, w1);
            ffma2(vacc[2],  a0, w2); ffma2(vacc[3],  a0, w3);
            ffma2(vacc[4],  a1, w0); ffma2(vacc[5],  a1, w1);
            ffma2(vacc[6],  a1, w2); ffma2(vacc[7],  a1, w3);
            ffma2(vacc[8],  a2, w0); ffma2(vacc[9],  a2, w1);
            ffma2(vacc[10], a2, w2); ffma2(vacc[11], a2, w3);
        }
    };

    // clean transition: phase A loop ended with a barrier; scratch free to re-layout
    STAGE_USV(0, WBb[0], ABb[0]);
    __syncthreads();
#pragma unroll 1
    for (int c = 0; c < 128; c++) {               // usv: K=2048 in 16-chunks
        int cur = c & 1, nxt = cur ^ 1;
        if (c < 127) STAGE_USV(c + 1, WBb[nxt], ABb[nxt]);
        else         STAGE_UVS(0, WBb[nxt], ABb[nxt]);
        COMPUTE_B(WBb[cur], ABb[cur]);
        __syncthreads();
    }
#pragma unroll 1
    for (int c = 0; c < 128; c++) {               // uvs: K=2048 in 16-chunks
        int cur = c & 1, nxt = cur ^ 1;            // continues parity (128 even)
        if (c < 127) STAGE_UVS(c + 1, WBb[nxt], ABb[nxt]);
        COMPUTE_B(WBb[cur], ABb[cur]);
        __syncthreads();
    }

    // u_v epilogue: mean over 96 per node (8 threads share pair tyB), gate, residual
    {
        ull psum = vacc[0];
#pragma unroll
        for (int q = 1; q < 12; q++) psum = fadd2(psum, vacc[q]);
        psum = fadd2(psum, __shfl_xor_sync(0xffffffffu, psum, 1));
        psum = fadd2(psum, __shfl_xor_sync(0xffffffffu, psum, 2));
        psum = fadd2(psum, __shfl_xor_sync(0xffffffffu, psum, 4));
        float2 pm = unpack2(psum);
        const float mean0 = pm.x * (1.0f / 96.0f);
        const float mean1 = pm.y * (1.0f / 96.0f);
        const int n0 = tyB * 2;
#pragma unroll
        for (int xx = 0; xx < 3; xx++) {
#pragma unroll
            for (int q = 0; q < 4; q++) {
                int o = txB * 4 + q; int idx = o * 3 + xx;
                float gw = __ldg(guw + idx), gb = __ldg(gub + idx);
                float2 u = unpack2(vacc[xx * 4 + q]);
                float g0 = sigmf(mean0 * gw + gb);
                float g1 = sigmf(mean1 * gw + gb);
                g_nv[(size_t)(node0 + n0) * 96 + idx]     = nv_s[n0 * 97 + idx] + u.x * g0;
                g_nv[(size_t)(node0 + n0 + 1) * 96 + idx] = nv_s[(n0 + 1) * 97 + idx] + u.y * g1;
            }
        }
    }
}

// ============================ k_out: out = ns @ W_out / 8 ============================
__global__ __launch_bounds__(256) void k_out(const float* __restrict__ Wout,
                                             float* __restrict__ out) {
    __shared__ float s_w[32 * 256];
    __shared__ float s_ns[16 * 64];
    const int tid = threadIdx.x;
    const int node0 = blockIdx.x * 16;
#pragma unroll
    for (int r = 0; r < 4; r++) {
        int lin = tid + r * 256; int t = lin >> 6, i = lin & 63;
        s_ns[t * 64 + i] = g_ns[(size_t)(node0 + t) * 64 + i];
    }
    float acc[16];
#pragma unroll
    for (int t = 0; t < 16; t++) acc[t] = 0.f;
    for (int ic = 0; ic < 2; ic++) {
        __syncthreads();
        const float4* wg = (const float4*)(Wout + (size_t)ic * 32 * 256);
        float4* ws4 = (float4*)s_w;
#pragma unroll
        for (int r = 0; r < 8; r++) ws4[tid + r * 256] = wg[tid + r * 256];
        __syncthreads();
#pragma unroll 8
        for (int i = 0; i < 32; i++) {
            float w = s_w[i * 256 + tid];
#pragma unroll
            for (int t = 0; t < 16; t++) acc[t] += s_ns[t * 64 + ic * 32 + i] * w;
        }
    }
#pragma unroll
    for (int t = 0; t < 16; t++)
        out[(size_t)(node0 + t) * 256 + tid] = acc[t] * INV8;
}

// =====================================================================================
extern "C" void kernel_launch(void* const* d_in, const int* in_sizes, int n_in,
                              void* d_out, int out_size) {
    const float* x    = (const float*)d_in[0];
    const float* eattr= (const float*)d_in[1];
    const float* Win  = (const float*)d_in[2];
    const float* Wout = (const float*)d_in[3];
    const float* Wss  = (const float*)d_in[4];
    const float* Wvv0 = (const float*)d_in[5];
    const float* Wsv  = (const float*)d_in[6];
    const float* Wvs  = (const float*)d_in[7];
    const float* gmw  = (const float*)d_in[8];
    const float* gmb  = (const float*)d_in[9];
    const float* Wuss = (const float*)d_in[10];
    const float* Wuvv = (const float*)d_in[11];
    const float* Wusv = (const float*)d_in[12];
    const float* Wuvs = (const float*)d_in[13];
    const float* guw  = (const float*)d_in[14];
    const float* gub  = (const float*)d_in[15];
    const int*   eidx = (const int*)d_in[16];
    float* out = (float*)d_out;

    void *p_nv = 0, *p_as = 0, *p_av = 0;
    cudaGetSymbolAddress(&p_nv, g_nv);
    cudaGetSymbolAddress(&p_as, g_as);
    cudaGetSymbolAddress(&p_av, g_av);

    cudaFuncSetAttribute(k_bilin, cudaFuncAttributeMaxDynamicSharedMemorySize, BILIN_SMEM);

    cudaMemsetAsync(p_nv, 0, sizeof(float) * NN * 96, 0);
    k_in<<<NN / 32, 256>>>(x, Win);

    for (int l = 0; l < 2; l++) {
        k_feat<<<NN / 8, 256>>>(Wss + l * 4096, Wvv0 + l * 2048,
                                Wsv + l * 2048, Wvs + l * 1024);
        cudaMemsetAsync(p_as, 0, sizeof(float) * NN * 64, 0);
        cudaMemsetAsync(p_av, 0, sizeof(float) * NN * 96, 0);
        k_edge<<<EE / 8, 256>>>(eattr, eidx, gmw + l * 96, gmb + l * 96);
        k_bilin<<<NN / 64, 256, BILIN_SMEM>>>(Wuss + (size_t)l * 262144,
                                              Wuvv + (size_t)l * 65536,
                                              Wusv + (size_t)l * 65536,
                                              Wuvs + (size_t)l * 65536,
                                              guw + l * 96, gub + l * 96);
    }
    k_out<<<NN / 16, 256>>>(Wout, out);
}

// round 12
// speedup vs baseline: 1.1461x; 1.1461x over previous
#include <cuda_runtime.h>
#include <math.h>
#include <stdint.h>

#define NN   32768
#define EE   1048576
#define NSD  64
#define NVD  32
#define LATD 256

// ---- scales ----
#define INV8    0.125f                 // 1/sqrt(64)
#define C1      0.10206207261596575f   // (1/sqrt(3))/sqrt(32) = 1/sqrt(96)
#define INV_R2  0.7071067811865476f
#define INVS32  0.17677669529663687f   // 1/sqrt(32)
#define S_USS   0.011048543456039806f  // 1/(64*sqrt(2))
#define S_UVV   0.012757998811063534f  // 1/(32*sqrt(6))
#define S_V     0.015625f              // 1/sqrt(64*32*2) = 1/64

typedef unsigned long long ull;

// ---- scratch (device globals; no allocation) ----
__device__ float g_ns[NN * NSD];
__device__ float g_nv[NN * NVD * 3];
__device__ float g_NF[(size_t)NN * 384];  // SS(64)|Q(3x64)|SV(32)|VS(3x32)
__device__ float g_as[NN * NSD];
__device__ float g_av[NN * NVD * 3];

__device__ __forceinline__ float sigmf(float x) { return 1.0f / (1.0f + __expf(-x)); }

// ---- packed f32x2 helpers ----
__device__ __forceinline__ void ffma2(ull& d, ull a, ull b) {
    asm("fma.rn.f32x2 %0, %1, %2, %0;" : "+l"(d) : "l"(a), "l"(b));
}
__device__ __forceinline__ ull fadd2(ull a, ull b) {
    ull r; asm("add.rn.f32x2 %0, %1, %2;" : "=l"(r) : "l"(a), "l"(b)); return r;
}
__device__ __forceinline__ ull pack2(float x, float y) {
    ull r;
    asm("mov.b64 %0, {%1, %2};" : "=l"(r)
        : "r"(__float_as_uint(x)), "r"(__float_as_uint(y)));
    return r;
}
__device__ __forceinline__ float2 unpack2(ull v) {
    unsigned int lo, hi;
    asm("mov.b64 {%0, %1}, %2;" : "=r"(lo), "=r"(hi) : "l"(v));
    return make_float2(__uint_as_float(lo), __uint_as_float(hi));
}

// ============================ k_in: ns = x @ W_in / 8 ============================
__global__ __launch_bounds__(256) void k_in(const float* __restrict__ x,
                                            const float* __restrict__ Win) {
    __shared__ float xs[32 * 65];
    __shared__ float ws[64 * 64];
    const int tid = threadIdx.x;
    const int node0 = blockIdx.x * 32;
    const float4* wg = (const float4*)Win;
    float4* ws4 = (float4*)ws;
#pragma unroll
    for (int r = 0; r < 4; r++) ws4[tid + r * 256] = wg[tid + r * 256];
#pragma unroll
    for (int r = 0; r < 8; r++) {
        int lin = tid + r * 256; int t = lin >> 6, i = lin & 63;
        xs[t * 65 + i] = x[(size_t)(node0 + t) * 64 + i];
    }
    __syncthreads();
    const int o = tid & 63, tq = tid >> 6;
    float acc[8] = {0, 0, 0, 0, 0, 0, 0, 0};
#pragma unroll 16
    for (int i = 0; i < 64; i++) {
        float w = ws[i * 64 + o];
#pragma unroll
        for (int tt = 0; tt < 8; tt++) acc[tt] += xs[(tq * 8 + tt) * 65 + i] * w;
    }
#pragma unroll
    for (int tt = 0; tt < 8; tt++)
        g_ns[(size_t)(node0 + tq * 8 + tt) * 64 + o] = acc[tt] * INV8;
}

// ============== k_feat: per-node precompute SS, Q, SV, VS ==============
__global__ __launch_bounds__(256) void k_feat(const float* __restrict__ Wss,
                                              const float* __restrict__ Wvv0,
                                              const float* __restrict__ Wsv,
                                              const float* __restrict__ Wvs) {
    __shared__ float s_wss[64 * 64];
    __shared__ float s_wvv[32 * 64];
    __shared__ float s_wsv[64 * 32];
    __shared__ float s_wvs[32 * 32];
    __shared__ float s_ns[8][64];
    __shared__ float s_nv[8][96];
    const int tid = threadIdx.x;
    for (int i = tid; i < 4096; i += 256) s_wss[i] = Wss[i];
    for (int i = tid; i < 2048; i += 256) s_wvv[i] = Wvv0[i];
    for (int i = tid; i < 2048; i += 256) s_wsv[i] = Wsv[i];
    for (int i = tid; i < 1024; i += 256) s_wvs[i] = Wvs[i];
    const int w = tid >> 5, lane = tid & 31;
    const int node = blockIdx.x * 8 + w;
#pragma unroll
    for (int r = 0; r < 2; r++) s_ns[w][lane + 32 * r] = g_ns[(size_t)node * 64 + lane + 32 * r];
#pragma unroll
    for (int r = 0; r < 3; r++) s_nv[w][lane + 32 * r] = g_nv[(size_t)node * 96 + lane + 32 * r];
    __syncthreads();
    float* nf = g_NF + (size_t)node * 384;
#pragma unroll
    for (int h = 0; h < 2; h++) {
        int o = lane + 32 * h;
        float a = 0;
#pragma unroll 8
        for (int i = 0; i < 64; i++) a += s_ns[w][i] * s_wss[i * 64 + o];
        nf[o] = a;
    }
#pragma unroll
    for (int xx = 0; xx < 3; xx++) {
#pragma unroll
        for (int h = 0; h < 2; h++) {
            int o = lane + 32 * h;
            float a = 0;
#pragma unroll 8
            for (int m = 0; m < 32; m++) a += s_nv[w][m * 3 + xx] * s_wvv[m * 64 + o];
            nf[64 + xx * 64 + o] = a;
        }
    }
    {
        float a = 0;
#pragma unroll 8
        for (int i = 0; i < 64; i++) a += s_ns[w][i] * s_wsv[i * 32 + lane];
        nf[256 + lane] = a;
    }
#pragma unroll
    for (int xx = 0; xx < 3; xx++) {
        float a = 0;
#pragma unroll 8
        for (int m = 0; m < 32; m++) a += s_nv[w][m * 3 + xx] * s_wvs[m * 32 + lane];
        nf[288 + xx * 32 + lane] = a;
    }
}

// ================= k_edge: per-edge message + gate + scatter-add =================
__global__ __launch_bounds__(256) void k_edge(const float* __restrict__ eattr,
                                              const int* __restrict__ eidx,
                                              const float* __restrict__ gmw,
                                              const float* __restrict__ gmb) {
    __shared__ float s_gw[96], s_gb[96];
    const int tid = threadIdx.x;
    if (tid < 96) { s_gw[tid] = gmw[tid]; s_gb[tid] = gmb[tid]; }
    __syncthreads();
    const int w = tid >> 5, lane = tid & 31;
    const int e = blockIdx.x * 8 + w;
    const int r = eidx[e];
    const int c = eidx[EE + e];
    const float ev0 = eattr[(size_t)e * 4 + 0];
    const float ev1 = eattr[(size_t)e * 4 + 1];
    const float ev2 = eattr[(size_t)e * 4 + 2];
    const float es  = eattr[(size_t)e * 4 + 3];
    const float* nf = g_NF + (size_t)c * 384;
    float ms[2];
#pragma unroll
    for (int h = 0; h < 2; h++) {
        int o = lane + 32 * h;
        float dot = ev0 * nf[64 + o] + ev1 * nf[128 + o] + ev2 * nf[192 + o];
        float v = (es * nf[o] * INV8 + dot * C1) * INV_R2;
        ms[h] = v * sigmf(v);
    }
    const float sv = nf[256 + lane];
    float mv0 = (sv * ev0 * INV8 + es * nf[288 + lane] * INVS32) * INV_R2;
    float mv1 = (sv * ev1 * INV8 + es * nf[320 + lane] * INVS32) * INV_R2;
    float mv2 = (sv * ev2 * INV8 + es * nf[352 + lane] * INVS32) * INV_R2;
    float p = mv0 + mv1 + mv2;
#pragma unroll
    for (int off = 16; off; off >>= 1) p += __shfl_xor_sync(0xffffffffu, p, off);
    const float mean = p * (1.0f / 96.0f);
    const float g0 = sigmf(mean * s_gw[lane * 3 + 0] + s_gb[lane * 3 + 0]);
    const float g1 = sigmf(mean * s_gw[lane * 3 + 1] + s_gb[lane * 3 + 1]);
    const float g2 = sigmf(mean * s_gw[lane * 3 + 2] + s_gb[lane * 3 + 2]);
    float* as = g_as + (size_t)r * 64;
    float* av = g_av + (size_t)r * 96;
    atomicAdd(as + lane,        ms[0]);
    atomicAdd(as + lane + 32,   ms[1]);
    atomicAdd(av + lane * 3 + 0, mv0 * g0);
    atomicAdd(av + lane * 3 + 1, mv1 * g1);
    atomicAdd(av + lane * 3 + 2, mv2 * g2);
}

// ====== k_bilin: four bilinears + gate + residual ======
// 64 nodes / block, 256 threads, 2 blocks/SM. R10 skeleton (kb=32, stage/sync/compute/sync).
// Phase A retiled: 8 outs x 4 nodes x half-K per thread; f32x2 lanes = OUT PAIR
// (W read directly as ull pairs, A broadcast-packed). Half-K partials reduced via smem.
// Phase B identical to R10.
// smem floats: ns 4160 | as 4160 | nv 6208 | av 6208 | scr 7168 = 27904 (109KB)
#define BILIN_SMEM (27904 * 4)

__global__ __launch_bounds__(256, 2) void k_bilin(const float* __restrict__ Wuss,
                                                  const float* __restrict__ Wuvv,
                                                  const float* __restrict__ Wusv,
                                                  const float* __restrict__ Wuvs,
                                                  const float* __restrict__ guw,
                                                  const float* __restrict__ gub) {
    extern __shared__ float sm[];
    float* ns_s = sm;                 // [64][65]
    float* as_s = sm + 4160;          // [64][65]
    float* nv_s = sm + 8320;          // [64][97]
    float* av_s = sm + 14528;         // [64][97]
    float* scr  = sm + 20736;         // 7168 floats (W + A staging, reused per phase)
    const int tid = threadIdx.x;
    const int node0 = blockIdx.x * 64;

    // ---- load node data (vectorized) ----
    {
        const float4* gns = (const float4*)(g_ns + (size_t)node0 * 64);
        const float4* gas = (const float4*)(g_as + (size_t)node0 * 64);
#pragma unroll
        for (int r = 0; r < 4; r++) {
            int lin = tid + r * 256; int t = lin >> 4, c = lin & 15;
            float4 v = gns[lin];
            float4 u = gas[lin];
            float* pd = ns_s + t * 65 + c * 4;
            pd[0] = v.x; pd[1] = v.y; pd[2] = v.z; pd[3] = v.w;
            float* qd = as_s + t * 65 + c * 4;
            qd[0] = u.x; qd[1] = u.y; qd[2] = u.z; qd[3] = u.w;
        }
        const float4* gnv = (const float4*)(g_nv + (size_t)node0 * 96);
        const float4* gav = (const float4*)(g_av + (size_t)node0 * 96);
#pragma unroll
        for (int r = 0; r < 6; r++) {
            int lin = tid + r * 256; int t = lin / 24, c = lin % 24;
            float4 v = gnv[lin];
            float4 u = gav[lin];
            float* pd = nv_s + t * 97 + c * 4;
            pd[0] = v.x; pd[1] = v.y; pd[2] = v.z; pd[3] = v.w;
            float* qd = av_s + t * 97 + c * 4;
            qd[0] = u.x; qd[1] = u.y; qd[2] = u.z; qd[3] = u.w;
        }
    }
    __syncthreads();

    // ================ Phase A: u_s = uss + uvv ================
    // thread tile: 8 outs (txA, as 4 out-pairs in f32x2 lanes) x 4 nodes (tyA) x half-K (khA)
    const int txA = tid & 7;           // outs 8*txA .. 8*txA+7
    const int tyA = (tid >> 3) & 15;   // nodes 4*tyA .. 4*tyA+3
    const int khA = tid >> 7;          // K half: kk in [16*khA, 16*khA+16)
    float* W_s = scr;            // [32][64], pre-scaled
    float* A_s = scr + 2048;     // [32][64]
    ull acc[16];                 // acc[p*4+n]: out-pair p (outs 2p,2p+1 within group), node n
#pragma unroll
    for (int q = 0; q < 16; q++) acc[q] = 0ull;

    auto COMPUTE_A = [&](const float* Ws, const float* As) {
#pragma unroll 8
        for (int kq = 0; kq < 16; kq++) {
            const int kk = khA * 16 + kq;
            float4 a4 = *(const float4*)(As + kk * 64 + tyA * 4);
            ulonglong2 wA = *(const ulonglong2*)(Ws + kk * 64 + txA * 8);
            ulonglong2 wB = *(const ulonglong2*)(Ws + kk * 64 + txA * 8 + 4);
            ull an0 = pack2(a4.x, a4.x), an1 = pack2(a4.y, a4.y);
            ull an2 = pack2(a4.z, a4.z), an3 = pack2(a4.w, a4.w);
            ffma2(acc[0],  an0, wA.x); ffma2(acc[1],  an1, wA.x);
            ffma2(acc[2],  an2, wA.x); ffma2(acc[3],  an3, wA.x);
            ffma2(acc[4],  an0, wA.y); ffma2(acc[5],  an1, wA.y);
            ffma2(acc[6],  an2, wA.y); ffma2(acc[7],  an3, wA.y);
            ffma2(acc[8],  an0, wB.x); ffma2(acc[9],  an1, wB.x);
            ffma2(acc[10], an2, wB.x); ffma2(acc[11], an3, wB.x);
            ffma2(acc[12], an0, wB.y); ffma2(acc[13], an1, wB.y);
            ffma2(acc[14], an2, wB.y); ffma2(acc[15], an3, wB.y);
        }
    };

    // --- uss: K = 4096, A[t,k] = ns[t,i]*as[t,j], k=(i<<6)|j ---
    for (int kb = 0; kb < 4096; kb += 32) {
        const float4* wg = (const float4*)(Wuss + (size_t)kb * 64);
        float4* ws4 = (float4*)W_s;
#pragma unroll
        for (int rr = 0; rr < 2; rr++) {
            float4 w = wg[tid + rr * 256];
            w.x *= S_USS; w.y *= S_USS; w.z *= S_USS; w.w *= S_USS;
            ws4[tid + rr * 256] = w;
        }
#pragma unroll
        for (int rr = 0; rr < 8; rr++) {
            int lin = tid + rr * 256; int kk = lin >> 6, t = lin & 63;
            int k = kb + kk; int i = k >> 6, j = k & 63;
            A_s[kk * 64 + t] = ns_s[t * 65 + i] * as_s[t * 65 + j];
        }
        __syncthreads();
        COMPUTE_A(W_s, A_s);
        __syncthreads();
    }
    // --- uvv: K = 3*1024 (x outer), A = nv[t,m,x]*av[t,n,x], k=(m<<5)|n ---
    for (int kb = 0; kb < 3072; kb += 32) {
        int xx = kb >> 10, km = kb & 1023;
        const float4* wg = (const float4*)(Wuvv + (size_t)km * 64);
        float4* ws4 = (float4*)W_s;
#pragma unroll
        for (int rr = 0; rr < 2; rr++) {
            float4 w = wg[tid + rr * 256];
            w.x *= S_UVV; w.y *= S_UVV; w.z *= S_UVV; w.w *= S_UVV;
            ws4[tid + rr * 256] = w;
        }
#pragma unroll
        for (int rr = 0; rr < 8; rr++) {
            int lin = tid + rr * 256; int kk = lin >> 6, t = lin & 63;
            int k = km + kk; int m = k >> 5, n = k & 31;
            A_s[kk * 64 + t] = nv_s[t * 97 + m * 3 + xx] * av_s[t * 97 + n * 3 + xx];
        }
        __syncthreads();
        COMPUTE_A(W_s, A_s);
        __syncthreads();
    }

    // ---- half-K reduction: kh=1 dumps partials, kh=0 adds + epilogue ----
    {
        ull* red = (ull*)scr;    // 128 threads x 16 ull = 2048 ull = 4096 floats (fits 7168)
        if (khA == 1) {
            const int base = (tid & 127) * 16;
#pragma unroll
            for (int q = 0; q < 16; q++) red[base + q] = acc[q];
        }
        __syncthreads();
        if (khA == 0) {
            const int base = tid * 16;
#pragma unroll
            for (int q = 0; q < 16; q++) acc[q] = fadd2(acc[q], red[base + q]);
            // u_s epilogue: silu + residual -> global ns (ns_s stays intact for phase B)
#pragma unroll
            for (int n = 0; n < 4; n++) {
                const int t = tyA * 4 + n;
                float* gp = g_ns + (size_t)(node0 + t) * 64 + txA * 8;
#pragma unroll
                for (int p = 0; p < 4; p++) {
                    float2 u = unpack2(acc[p * 4 + n]);
                    const int o0 = txA * 8 + 2 * p;
                    float2 w;
                    w.x = ns_s[t * 65 + o0]     + u.x * sigmf(u.x);
                    w.y = ns_s[t * 65 + o0 + 1] + u.y * sigmf(u.y);
                    *(float2*)(gp + 2 * p) = w;
                }
            }
        }
        __syncthreads();   // protect scr before phase B staging reuses it
    }

    // ================ Phase B: u_v = usv + uvs (identical to R10) ================
    // thread tile: 4 outs (txB) x 2 nodes (f32x2 pair, tyB) x 3 x-components
    const int txB = tid & 7, tyB = tid >> 3;
    float* WB = scr;             // [32][32], pre-scaled
    float* AB = scr + 1024;      // [3][32][64]
    ull vacc[12];
#pragma unroll
    for (int q = 0; q < 12; q++) vacc[q] = 0ull;

    // --- usv: K = 2048 per x, A(x)[t,k] = ns[t,i]*av[t,n,x], k=(i<<5)|n ---
    for (int kb = 0; kb < 2048; kb += 32) {
        {
            float4 w = ((const float4*)(Wusv + (size_t)kb * 32))[tid];
            w.x *= S_V; w.y *= S_V; w.z *= S_V; w.w *= S_V;
            ((float4*)WB)[tid] = w;
        }
#pragma unroll
        for (int rr = 0; rr < 24; rr++) {
            int lin = tid + rr * 256;
            int xx = lin >> 11; int rem = lin & 2047; int kk = rem >> 6, t = rem & 63;
            int k = kb + kk; int i = k >> 5, n = k & 31;
            AB[xx * 2048 + kk * 64 + t] = ns_s[t * 65 + i] * av_s[t * 97 + n * 3 + xx];
        }
        __syncthreads();
#pragma unroll 8
        for (int kk = 0; kk < 32; kk++) {
            float4 w4 = *(const float4*)(WB + kk * 32 + txB * 4);
            ull w0 = pack2(w4.x, w4.x), w1 = pack2(w4.y, w4.y);
            ull w2 = pack2(w4.z, w4.z), w3 = pack2(w4.w, w4.w);
            ull a0 = *(const ull*)(AB + kk * 64 + tyB * 2);
            ull a1 = *(const ull*)(AB + 2048 + kk * 64 + tyB * 2);
            ull a2 = *(const ull*)(AB + 4096 + kk * 64 + tyB * 2);
            ffma2(vacc[0],  a0, w0); ffma2(vacc[1],  a0, w1);
            ffma2(vacc[2],  a0, w2); ffma2(vacc[3],  a0, w3);
            ffma2(vacc[4],  a1, w0); ffma2(vacc[5],  a1, w1);
            ffma2(vacc[6],  a1, w2); ffma2(vacc[7],  a1, w3);
            ffma2(vacc[8],  a2, w0); ffma2(vacc[9],  a2, w1);
            ffma2(vacc[10], a2, w2); ffma2(vacc[11], a2, w3);
        }
        __syncthreads();
    }
    // --- uvs: K = 2048 per x, A(x)[t,k] = nv[t,m,x]*as[t,j], k=(m<<6)|j ---
    for (int kb = 0; kb < 2048; kb += 32) {
        {
            float4 w = ((const float4*)(Wuvs + (size_t)kb * 32))[tid];
            w.x *= S_V; w.y *= S_V; w.z *= S_V; w.w *= S_V;
            ((float4*)WB)[tid] = w;
        }
#pragma unroll
        for (int rr = 0; rr < 24; rr++) {
            int lin = tid + rr * 256;
            int xx = lin >> 11; int rem = lin & 2047; int kk = rem >> 6, t = rem & 63;
            int k = kb + kk; int m = k >> 6, j = k & 63;
            AB[xx * 2048 + kk * 64 + t] = nv_s[t * 97 + m * 3 + xx] * as_s[t * 65 + j];
        }
        __syncthreads();
#pragma unroll 8
        for (int kk = 0; kk < 32; kk++) {
            float4 w4 = *(const float4*)(WB + kk * 32 + txB * 4);
            ull w0 = pack2(w4.x, w4.x), w1 = pack2(w4.y, w4.y);
            ull w2 = pack2(w4.z, w4.z), w3 = pack2(w4.w, w4.w);
            ull a0 = *(const ull*)(AB + kk * 64 + tyB * 2);
            ull a1 = *(const ull*)(AB + 2048 + kk * 64 + tyB * 2);
            ull a2 = *(const ull*)(AB + 4096 + kk * 64 + tyB * 2);
            ffma2(vacc[0],  a0, w0); ffma2(vacc[1],  a0, w1);
            ffma2(vacc[2],  a0, w2); ffma2(vacc[3],  a0, w3);
            ffma2(vacc[4],  a1, w0); ffma2(vacc[5],  a1, w1);
            ffma2(vacc[6],  a1, w2); ffma2(vacc[7],  a1, w3);
            ffma2(vacc[8],  a2, w0); ffma2(vacc[9],  a2, w1);
            ffma2(vacc[10], a2, w2); ffma2(vacc[11], a2, w3);
        }
        __syncthreads();
    }

    // u_v epilogue: mean over 96 per node (8 threads share pair tyB), gate, residual
    {
        ull psum = vacc[0];
#pragma unroll
        for (int q = 1; q < 12; q++) psum = fadd2(psum, vacc[q]);
        psum = fadd2(psum, __shfl_xor_sync(0xffffffffu, psum, 1));
        psum = fadd2(psum, __shfl_xor_sync(0xffffffffu, psum, 2));
        psum = fadd2(psum, __shfl_xor_sync(0xffffffffu, psum, 4));
        float2 pm = unpack2(psum);
        const float mean0 = pm.x * (1.0f / 96.0f);
        const float mean1 = pm.y * (1.0f / 96.0f);
        const int n0 = tyB * 2;
#pragma unroll
        for (int xx = 0; xx < 3; xx++) {
#pragma unroll
            for (int q = 0; q < 4; q++) {
                int o = txB * 4 + q; int idx = o * 3 + xx;
                float gw = __ldg(guw + idx), gb = __ldg(gub + idx);
                float2 u = unpack2(vacc[xx * 4 + q]);
                float g0 = sigmf(mean0 * gw + gb);
                float g1 = sigmf(mean1 * gw + gb);
                g_nv[(size_t)(node0 + n0) * 96 + idx]     = nv_s[n0 * 97 + idx] + u.x * g0;
                g_nv[(size_t)(node0 + n0 + 1) * 96 + idx] = nv_s[(n0 + 1) * 97 + idx] + u.y * g1;
            }
        }
    }
}

// ============================ k_out: out = ns @ W_out / 8 ============================
__global__ __launch_bounds__(256) void k_out(const float* __restrict__ Wout,
                                             float* __restrict__ out) {
    __shared__ float s_w[32 * 256];
    __shared__ float s_ns[16 * 64];
    const int tid = threadIdx.x;
    const int node0 = blockIdx.x * 16;
#pragma unroll
    for (int r = 0; r < 4; r++) {
        int lin = tid + r * 256; int t = lin >> 6, i = lin & 63;
        s_ns[t * 64 + i] = g_ns[(size_t)(node0 + t) * 64 + i];
    }
    float acc[16];
#pragma unroll
    for (int t = 0; t < 16; t++) acc[t] = 0.f;
    for (int ic = 0; ic < 2; ic++) {
        __syncthreads();
        const float4* wg = (const float4*)(Wout + (size_t)ic * 32 * 256);
        float4* ws4 = (float4*)s_w;
#pragma unroll
        for (int r = 0; r < 8; r++) ws4[tid + r * 256] = wg[tid + r * 256];
        __syncthreads();
#pragma unroll 8
        for (int i = 0; i < 32; i++) {
            float w = s_w[i * 256 + tid];
#pragma unroll
            for (int t = 0; t < 16; t++) acc[t] += s_ns[t * 64 + ic * 32 + i] * w;
        }
    }
#pragma unroll
    for (int t = 0; t < 16; t++)
        out[(size_t)(node0 + t) * 256 + tid] = acc[t] * INV8;
}

// =====================================================================================
extern "C" void kernel_launch(void* const* d_in, const int* in_sizes, int n_in,
                              void* d_out, int out_size) {
    const float* x    = (const float*)d_in[0];
    const float* eattr= (const float*)d_in[1];
    const float* Win  = (const float*)d_in[2];
    const float* Wout = (const float*)d_in[3];
    const float* Wss  = (const float*)d_in[4];
    const float* Wvv0 = (const float*)d_in[5];
    const float* Wsv  = (const float*)d_in[6];
    const float* Wvs  = (const float*)d_in[7];
    const float* gmw  = (const float*)d_in[8];
    const float* gmb  = (const float*)d_in[9];
    const float* Wuss = (const float*)d_in[10];
    const float* Wuvv = (const float*)d_in[11];
    const float* Wusv = (const float*)d_in[12];
    const float* Wuvs = (const float*)d_in[13];
    const float* guw  = (const float*)d_in[14];
    const float* gub  = (const float*)d_in[15];
    const int*   eidx = (const int*)d_in[16];
    float* out = (float*)d_out;

    void *p_nv = 0, *p_as = 0, *p_av = 0;
    cudaGetSymbolAddress(&p_nv, g_nv);
    cudaGetSymbolAddress(&p_as, g_as);
    cudaGetSymbolAddress(&p_av, g_av);

    cudaFuncSetAttribute(k_bilin, cudaFuncAttributeMaxDynamicSharedMemorySize, BILIN_SMEM);

    cudaMemsetAsync(p_nv, 0, sizeof(float) * NN * 96, 0);
    k_in<<<NN / 32, 256>>>(x, Win);

    for (int l = 0; l < 2; l++) {
        k_feat<<<NN / 8, 256>>>(Wss + l * 4096, Wvv0 + l * 2048,
                                Wsv + l * 2048, Wvs + l * 1024);
        cudaMemsetAsync(p_as, 0, sizeof(float) * NN * 64, 0);
        cudaMemsetAsync(p_av, 0, sizeof(float) * NN * 96, 0);
        k_edge<<<EE / 8, 256>>>(eattr, eidx, gmw + l * 96, gmb + l * 96);
        k_bilin<<<NN / 64, 256, BILIN_SMEM>>>(Wuss + (size_t)l * 262144,
                                              Wuvv + (size_t)l * 65536,
                                              Wusv + (size_t)l * 65536,
                                              Wuvs + (size_t)l * 65536,
                                              guw + l * 96, gub + l * 96);
    }
    k_out<<<NN / 16, 256>>>(Wout, out);
}